// round 16
// baseline (speedup 1.0000x reference)
#include <cuda_runtime.h>
#include <cuda_bf16.h>

// Packed fp32x2 FMA (Blackwell sm_100+). Only reachable via PTX.
__device__ __forceinline__ void fma2(unsigned long long& d,
                                     unsigned long long a,
                                     unsigned long long b) {
    asm("fma.rn.f32x2 %0, %1, %2, %0;" : "+l"(d) : "l"(a), "l"(b));
}

// ---------------------------------------------------------------------------
// Fused kernel, 256 threads/CTA, 2 CTAs/SM.
// gid 0        : logdet tail (runs in wave 1, hidden under conv CTAs).
// gid 1..4096  : block-diagonal 1x1 conv.
//   z[b, k*32+d, p] = sum_c w[k, d, c] * x[b, k*32+c, p]
//   CTA = 64 pixel-threads x 4 d-groups (8 outputs each), 8 px/thread
//   as two coalesced pixel-quads (A at tpix, B at tpix+64 ull2 slots).
//   Per warp per c: 2 LDG.128 + 4 LDS.128 per 32 FMA2 (25% issue overhead).
//   Rotating depth-3 register prefetch on each quad stream (MLP=6/warp).
// ---------------------------------------------------------------------------
__global__ __launch_bounds__(256, 2)
void fused_kernel(const float* __restrict__ x,
                  const float* __restrict__ w,
                  const float* __restrict__ ld_in,
                  float* __restrict__ out,
                  long zn) {
    __shared__ union SM {
        ulonglong2 w2[512];                 // conv: packed weight pairs (8 KB)
        struct {
            float A[8][32][33];             // logdet: padded matrices
            float lds[8];
        } lu;
    } sm;

    const int gid = blockIdx.x;
    const int tid = threadIdx.x;

    if (gid != 0) {
        // ---------------- conv path ----------------
        const int g4    = gid - 1;
        const int chunk = g4 & 31;          // 32 chunks of 512 px per plane
        const int k     = (g4 >> 5) & 7;
        const int b     = g4 >> 8;

        // Pack weights: ulonglong2 sm.w2[c*16 + dp] =
        //   { pack2(w[2dp][c]), pack2(w[2dp+1][c]) },  dp in [0,16)
        unsigned long long* w2u = reinterpret_cast<unsigned long long*>(sm.w2);
        const float* wk = w + k * 1024;
        for (int i = tid; i < 1024; i += 256) {          // i = d*32 + c
            const int d = i >> 5, c = i & 31;
            const unsigned long long u =
                (unsigned long long)__float_as_uint(wk[i]);
            w2u[(c * 16 + (d >> 1)) * 2 + (d & 1)] = (u << 32) | u;
        }
        __syncthreads();

        const int  tpix  = tid & 63;        // pixel-thread within CTA
        const int  g     = tid >> 6;        // d-group: outputs [8g, 8g+8)
        const long pidx  = (long)chunk * 128 + tpix;     // ulonglong2 index
        const long base4 = ((long)b * 256 + (long)k * 32) * 4096L;

        // Quad stream A at pidx, quad stream B at pidx + 64 (ull2 units).
        const ulonglong2* __restrict__ xp =
            reinterpret_cast<const ulonglong2*>(x) + base4 + pidx;

        // 8 outputs x 2 quads x 2 f32x2 = 32 ull accumulators (64 regs)
        unsigned long long accA[16], accB[16];
#pragma unroll
        for (int i = 0; i < 16; ++i) { accA[i] = 0ULL; accB[i] = 0ULL; }

        const ulonglong2* __restrict__ wg = sm.w2 + g * 4;

        // Rotating register prefetch: 3 channel-planes x 2 quads in flight.
        ulonglong2 bufA[3], bufB[3];
#pragma unroll
        for (int j = 0; j < 3; ++j) {
            bufA[j] = xp[(long)j * 4096];
            bufB[j] = xp[(long)j * 4096 + 64];
        }

#pragma unroll
        for (int c = 0; c < 32; ++c) {
            const int slot = c % 3;
            const ulonglong2 xa = bufA[slot];
            const ulonglong2 xb = bufB[slot];
            if (c < 29) {                                 // prefetch c+3
                bufA[slot] = xp[(long)(c + 3) * 4096];
                bufB[slot] = xp[(long)(c + 3) * 4096 + 64];
            }
            const ulonglong2* wr = wg + c * 16;
#pragma unroll
            for (int j = 0; j < 4; ++j) {
                const ulonglong2 wv = wr[j];            // LDS.128 broadcast
                fma2(accA[4 * j + 0], xa.x, wv.x);
                fma2(accA[4 * j + 1], xa.y, wv.x);
                fma2(accA[4 * j + 2], xa.x, wv.y);
                fma2(accA[4 * j + 3], xa.y, wv.y);
                fma2(accB[4 * j + 0], xb.x, wv.x);
                fma2(accB[4 * j + 1], xb.y, wv.x);
                fma2(accB[4 * j + 2], xb.x, wv.y);
                fma2(accB[4 * j + 3], xb.y, wv.y);
            }
        }

        ulonglong2* __restrict__ zp =
            reinterpret_cast<ulonglong2*>(out) + base4 + pidx +
            (long)(8 * g) * 4096;
#pragma unroll
        for (int j = 0; j < 4; ++j) {
            zp[(long)(2 * j)     * 4096]      = make_ulonglong2(accA[4 * j + 0], accA[4 * j + 1]);
            zp[(long)(2 * j + 1) * 4096]      = make_ulonglong2(accA[4 * j + 2], accA[4 * j + 3]);
            zp[(long)(2 * j)     * 4096 + 64] = make_ulonglong2(accB[4 * j + 0], accB[4 * j + 1]);
            zp[(long)(2 * j + 1) * 4096 + 64] = make_ulonglong2(accB[4 * j + 2], accB[4 * j + 3]);
        }
    } else {
        // ---------------- logdet path (gid 0, runs in wave 1) ----------------
        // Warps 0..7: LU w/ partial pivot on matrix m = warp id.
        // Reference discards the sign: log|det| = sum log|pivot|.
        const int m    = tid >> 5;
        const int lane = tid & 31;

        for (int r = 0; r < 32; ++r)
            sm.lu.A[m][r][lane] = w[m * 1024 + r * 32 + lane];
        __syncwarp();

        float prod = 1.0f;   // product of pivot mantissas in [1,2)
        int   esum = 0;      // sum of pivot exponents
        for (int step = 0; step < 32; ++step) {
            // argmax |A[r][step]|, r >= step (abs-bits compare as uint)
            const unsigned v = (lane >= step)
                ? (__float_as_uint(sm.lu.A[m][lane][step]) & 0x7fffffffu)
                : 0u;
            const unsigned mx  = __reduce_max_sync(0xffffffffu, v);
            const unsigned bal = __ballot_sync(0xffffffffu, v == mx);
            const int pr = __ffs(bal) - 1;

            if (pr != step) {                // swap rows (lane owns a column)
                const float tswap = sm.lu.A[m][step][lane];
                sm.lu.A[m][step][lane] = sm.lu.A[m][pr][lane];
                sm.lu.A[m][pr][lane]   = tswap;
            }
            __syncwarp();

            const float piv = sm.lu.A[m][step][step];
            const unsigned pb = __float_as_uint(piv) & 0x7fffffffu;
            esum += (int)(pb >> 23) - 127;
            prod *= __uint_as_float((pb & 0x007fffffu) | 0x3f800000u);

            const float inv = 1.0f / piv;
            if (lane > step) {
                const float f = sm.lu.A[m][lane][step] * inv;
                for (int c2 = step + 1; c2 < 32; ++c2)
                    sm.lu.A[m][lane][c2] -= f * sm.lu.A[m][step][c2];
            }
            __syncwarp();
        }
        if (lane == 0)
            sm.lu.lds[m] = (float)esum * 0.6931471805599453f + logf(prod);
        __syncthreads();

        if (tid < 16) {
            float tot = 0.0f;
#pragma unroll
            for (int mm = 0; mm < 8; ++mm) tot += sm.lu.lds[mm];
            out[zn + tid] = ld_in[tid] + tot * 16384.0f;
        }
    }
}

// ---------------------------------------------------------------------------
extern "C" void kernel_launch(void* const* d_in, const int* in_sizes, int n_in,
                              void* d_out, int out_size) {
    const float* x  = (const float*)d_in[0];   // [16, 256, 128, 128]
    const float* w  = (const float*)d_in[1];   // [8, 32, 32]
    const float* ld = (const float*)d_in[2];   // [16]
    float* out = (float*)d_out;

    const long zn = (long)in_sizes[0];         // element count of z

    fused_kernel<<<4097, 256>>>(x, w, ld, out, zn);
    (void)n_in; (void)out_size;
}

// round 17
// speedup vs baseline: 1.0142x; 1.0142x over previous
#include <cuda_runtime.h>
#include <cuda_bf16.h>

// Packed fp32x2 FMA (Blackwell sm_100+). Only reachable via PTX.
__device__ __forceinline__ void fma2(unsigned long long& d,
                                     unsigned long long a,
                                     unsigned long long b) {
    asm("fma.rn.f32x2 %0, %1, %2, %0;" : "+l"(d) : "l"(a), "l"(b));
}

// ---------------------------------------------------------------------------
// Fused kernel, 256 threads/CTA, 2 CTAs/SM.
// gid 0        : logdet tail (runs in wave 1, hidden under conv CTAs).
// gid 1..4096  : block-diagonal 1x1 conv.
//   z[b, k*32+d, p] = sum_c w[k, d, c] * x[b, k*32+c, p]
//   CTA = 64 pixel-threads x 4 d-groups (8 outputs each), 8 px/thread
//   as two coalesced pixel-quads (A at tpix, B at tpix+64 ull2 slots).
//   Per warp per c: 2 LDG.128 + 4 LDS.128 per 32 FMA2 (25% issue overhead).
//   Rotating depth-3 register prefetch on each quad stream (MLP=6/warp).
// ---------------------------------------------------------------------------
__global__ __launch_bounds__(256, 2)
void fused_kernel(const float* __restrict__ x,
                  const float* __restrict__ w,
                  const float* __restrict__ ld_in,
                  float* __restrict__ out,
                  long zn) {
    __shared__ union SM {
        ulonglong2 w2[512];                 // conv: packed weight pairs (8 KB)
        struct {
            float A[8][32][33];             // logdet: padded matrices
            float lds[8];
        } lu;
    } sm;

    const int gid = blockIdx.x;
    const int tid = threadIdx.x;

    if (gid != 0) {
        // ---------------- conv path ----------------
        const int g4    = gid - 1;
        const int chunk = g4 & 31;          // 32 chunks of 512 px per plane
        const int k     = (g4 >> 5) & 7;
        const int b     = g4 >> 8;

        // Pack weights: ulonglong2 sm.w2[c*16 + dp] =
        //   { pack2(w[2dp][c]), pack2(w[2dp+1][c]) },  dp in [0,16)
        unsigned long long* w2u = reinterpret_cast<unsigned long long*>(sm.w2);
        const float* wk = w + k * 1024;
        for (int i = tid; i < 1024; i += 256) {          // i = d*32 + c
            const int d = i >> 5, c = i & 31;
            const unsigned long long u =
                (unsigned long long)__float_as_uint(wk[i]);
            w2u[(c * 16 + (d >> 1)) * 2 + (d & 1)] = (u << 32) | u;
        }
        __syncthreads();

        const int  tpix  = tid & 63;        // pixel-thread within CTA
        const int  g     = tid >> 6;        // d-group: outputs [8g, 8g+8)
        const long pidx  = (long)chunk * 128 + tpix;     // ulonglong2 index
        const long base4 = ((long)b * 256 + (long)k * 32) * 4096L;

        // Quad stream A at pidx, quad stream B at pidx + 64 (ull2 units).
        const ulonglong2* __restrict__ xp =
            reinterpret_cast<const ulonglong2*>(x) + base4 + pidx;

        // 8 outputs x 2 quads x 2 f32x2 = 32 ull accumulators (64 regs)
        unsigned long long accA[16], accB[16];
#pragma unroll
        for (int i = 0; i < 16; ++i) { accA[i] = 0ULL; accB[i] = 0ULL; }

        const ulonglong2* __restrict__ wg = sm.w2 + g * 4;

        // Rotating register prefetch: 3 channel-planes x 2 quads in flight.
        ulonglong2 bufA[3], bufB[3];
#pragma unroll
        for (int j = 0; j < 3; ++j) {
            bufA[j] = xp[(long)j * 4096];
            bufB[j] = xp[(long)j * 4096 + 64];
        }

#pragma unroll
        for (int c = 0; c < 32; ++c) {
            const int slot = c % 3;
            const ulonglong2 xa = bufA[slot];
            const ulonglong2 xb = bufB[slot];
            if (c < 29) {                                 // prefetch c+3
                bufA[slot] = xp[(long)(c + 3) * 4096];
                bufB[slot] = xp[(long)(c + 3) * 4096 + 64];
            }
            const ulonglong2* wr = wg + c * 16;
#pragma unroll
            for (int j = 0; j < 4; ++j) {
                const ulonglong2 wv = wr[j];            // LDS.128 broadcast
                fma2(accA[4 * j + 0], xa.x, wv.x);
                fma2(accA[4 * j + 1], xa.y, wv.x);
                fma2(accA[4 * j + 2], xa.x, wv.y);
                fma2(accA[4 * j + 3], xa.y, wv.y);
                fma2(accB[4 * j + 0], xb.x, wv.x);
                fma2(accB[4 * j + 1], xb.y, wv.x);
                fma2(accB[4 * j + 2], xb.x, wv.y);
                fma2(accB[4 * j + 3], xb.y, wv.y);
            }
        }

        ulonglong2* __restrict__ zp =
            reinterpret_cast<ulonglong2*>(out) + base4 + pidx +
            (long)(8 * g) * 4096;
#pragma unroll
        for (int j = 0; j < 4; ++j) {
            zp[(long)(2 * j)     * 4096]      = make_ulonglong2(accA[4 * j + 0], accA[4 * j + 1]);
            zp[(long)(2 * j + 1) * 4096]      = make_ulonglong2(accA[4 * j + 2], accA[4 * j + 3]);
            zp[(long)(2 * j)     * 4096 + 64] = make_ulonglong2(accB[4 * j + 0], accB[4 * j + 1]);
            zp[(long)(2 * j + 1) * 4096 + 64] = make_ulonglong2(accB[4 * j + 2], accB[4 * j + 3]);
        }
    } else {
        // ---------------- logdet path (gid 0, runs in wave 1) ----------------
        // Warps 0..7: LU w/ partial pivot on matrix m = warp id.
        // Reference discards the sign: log|det| = sum log|pivot|.
        const int m    = tid >> 5;
        const int lane = tid & 31;

        for (int r = 0; r < 32; ++r)
            sm.lu.A[m][r][lane] = w[m * 1024 + r * 32 + lane];
        __syncwarp();

        float prod = 1.0f;   // product of pivot mantissas in [1,2)
        int   esum = 0;      // sum of pivot exponents
        for (int step = 0; step < 32; ++step) {
            // argmax |A[r][step]|, r >= step (abs-bits compare as uint)
            const unsigned v = (lane >= step)
                ? (__float_as_uint(sm.lu.A[m][lane][step]) & 0x7fffffffu)
                : 0u;
            const unsigned mx  = __reduce_max_sync(0xffffffffu, v);
            const unsigned bal = __ballot_sync(0xffffffffu, v == mx);
            const int pr = __ffs(bal) - 1;

            if (pr != step) {                // swap rows (lane owns a column)
                const float tswap = sm.lu.A[m][step][lane];
                sm.lu.A[m][step][lane] = sm.lu.A[m][pr][lane];
                sm.lu.A[m][pr][lane]   = tswap;
            }
            __syncwarp();

            const float piv = sm.lu.A[m][step][step];
            const unsigned pb = __float_as_uint(piv) & 0x7fffffffu;
            esum += (int)(pb >> 23) - 127;
            prod *= __uint_as_float((pb & 0x007fffffu) | 0x3f800000u);

            const float inv = 1.0f / piv;
            if (lane > step) {
                const float f = sm.lu.A[m][lane][step] * inv;
                for (int c2 = step + 1; c2 < 32; ++c2)
                    sm.lu.A[m][lane][c2] -= f * sm.lu.A[m][step][c2];
            }
            __syncwarp();
        }
        if (lane == 0)
            sm.lu.lds[m] = (float)esum * 0.6931471805599453f + logf(prod);
        __syncthreads();

        if (tid < 16) {
            float tot = 0.0f;
#pragma unroll
            for (int mm = 0; mm < 8; ++mm) tot += sm.lu.lds[mm];
            out[zn + tid] = ld_in[tid] + tot * 16384.0f;
        }
    }
}

// ---------------------------------------------------------------------------
extern "C" void kernel_launch(void* const* d_in, const int* in_sizes, int n_in,
                              void* d_out, int out_size) {
    const float* x  = (const float*)d_in[0];   // [16, 256, 128, 128]
    const float* w  = (const float*)d_in[1];   // [8, 32, 32]
    const float* ld = (const float*)d_in[2];   // [16]
    float* out = (float*)d_out;

    const long zn = (long)in_sizes[0];         // element count of z

    fused_kernel<<<4097, 256>>>(x, w, ld, out, zn);
    (void)n_in; (void)out_size;
}